// round 1
// baseline (speedup 1.0000x reference)
#include <cuda_runtime.h>
#include <cstdint>

#define MAX_N 100000
#define D 64

// Scratch (allocation-free rule: __device__ globals)
__device__ float g_deg[MAX_N];
__device__ float g_dis[MAX_N];
__device__ float g_h[(size_t)MAX_N * D];

// ---------------- degree ----------------

__global__ void k_init_deg(int n) {
    int i = blockIdx.x * blockDim.x + threadIdx.x;
    if (i < n) g_deg[i] = 1.0f;   // self-loop contributes 1
}

__global__ void k_edge_deg(const int* __restrict__ ei, int e) {
    int i = blockIdx.x * blockDim.x + threadIdx.x;
    if (i < e) {
        int s = ei[i];
        int d = ei[e + i];
        if (s != d) atomicAdd(&g_deg[d], 1.0f);
    }
}

// ---------------- GEMM h = x @ W^T, fused self-loop init + bias + dis ----------------
// Block: 256 threads = 16x16, computes a 64(rows) x 64(cols) tile with 4x4 register blocking.

__global__ __launch_bounds__(256) void k_gemm(
    const float* __restrict__ x, const float* __restrict__ w,
    const float* __restrict__ bias, float* __restrict__ out, int n)
{
    __shared__ float xs[64][65];   // xs[r][k]
    __shared__ float ws[64][65];   // ws[c][k]  (W is [c_out][c_in] row-major)

    int tid = threadIdx.x;
    int tx = tid & 15;       // col group
    int ty = tid >> 4;       // row group
    int rbase = blockIdx.x * 64;

    #pragma unroll
    for (int l = tid; l < 4096; l += 256)
        ws[l >> 6][l & 63] = w[l];

    #pragma unroll
    for (int l = tid; l < 4096; l += 256) {
        int r = l >> 6, k = l & 63;
        int gr = rbase + r;
        xs[r][k] = (gr < n) ? x[(size_t)gr * D + k] : 0.0f;
    }
    __syncthreads();

    float acc[4][4] = {};
    int r0 = ty * 4, c0 = tx * 4;

    #pragma unroll 16
    for (int k = 0; k < 64; k++) {
        float xv[4], wv[4];
        #pragma unroll
        for (int i = 0; i < 4; i++) xv[i] = xs[r0 + i][k];
        #pragma unroll
        for (int j = 0; j < 4; j++) wv[j] = ws[c0 + j][k];
        #pragma unroll
        for (int i = 0; i < 4; i++)
            #pragma unroll
            for (int j = 0; j < 4; j++)
                acc[i][j] += xv[i] * wv[j];
    }

    float bv[4];
    #pragma unroll
    for (int j = 0; j < 4; j++) bv[j] = bias[c0 + j];

    #pragma unroll
    for (int i = 0; i < 4; i++) {
        int gr = rbase + r0 + i;
        if (gr < n) {
            float ds = rsqrtf(g_deg[gr]);
            if (tx == 0) g_dis[gr] = ds;
            float sc = ds * ds;              // self-loop norm dis*dis
            #pragma unroll
            for (int j = 0; j < 4; j++) {
                float hv = acc[i][j];
                g_h[(size_t)gr * D + c0 + j] = hv;
                out[(size_t)gr * D + c0 + j] = hv * sc + bv[j];
            }
        }
    }
}

// ---------------- edge scatter ----------------
// 4 threads per edge; each handles 4 float4 chunks (64 floats total per edge).
// Vectorized no-return reductions: red.global.add.v4.f32 (sm_90+).

__global__ __launch_bounds__(256) void k_scatter(
    const int* __restrict__ ei, float* __restrict__ out, int e)
{
    int t = blockIdx.x * blockDim.x + threadIdx.x;
    int edge = t >> 2;
    if (edge >= e) return;
    int chunk = t & 3;

    int s = ei[edge];
    int d = ei[e + edge];
    if (s == d) return;                       // self-edges filtered (weight 0)

    float coef = g_dis[s] * g_dis[d];

    const float4* hp = reinterpret_cast<const float4*>(g_h + (size_t)s * D) + chunk * 4;
    float4*       op = reinterpret_cast<float4*>(out + (size_t)d * D) + chunk * 4;

    #pragma unroll
    for (int q = 0; q < 4; q++) {
        float4 v = hp[q];
        float a = coef * v.x, b = coef * v.y, c = coef * v.z, w = coef * v.w;
        asm volatile("red.global.add.v4.f32 [%0], {%1, %2, %3, %4};"
                     :: "l"(op + q), "f"(a), "f"(b), "f"(c), "f"(w)
                     : "memory");
    }
}

// ---------------- launch ----------------

extern "C" void kernel_launch(void* const* d_in, const int* in_sizes, int n_in,
                              void* d_out, int out_size) {
    const float* x    = (const float*)d_in[0];
    const int*   ei   = (const int*)d_in[1];
    const float* w    = (const float*)d_in[2];
    const float* bias = (const float*)d_in[3];
    float* out = (float*)d_out;

    int n = in_sizes[0] / D;    // 100000
    int e = in_sizes[1] / 2;    // 1000000

    k_init_deg<<<(n + 255) / 256, 256>>>(n);
    k_edge_deg<<<(e + 255) / 256, 256>>>(ei, e);
    k_gemm<<<(n + 63) / 64, 256>>>(x, w, bias, out, n);

    int st = e * 4;             // 4 threads per edge
    k_scatter<<<(st + 255) / 256, 256>>>(ei, out, e);
}

// round 2
// speedup vs baseline: 1.3794x; 1.3794x over previous
#include <cuda_runtime.h>
#include <cstdint>

#define MAX_N 100000
#define MAX_E 1000000
#define D 64
#define SCAN_BS 512
#define MAX_NB 256   // covers n up to 131072

// Scratch (allocation-free rule: __device__ globals)
__device__ int   g_cnt[MAX_N];        // in-degree excluding self edges
__device__ int   g_loc[MAX_N];        // block-local exclusive scan
__device__ int   g_bsum[MAX_NB];      // per-block sums
__device__ int   g_boff[MAX_NB];      // block offsets (exclusive)
__device__ int   g_off[MAX_N + 1];    // CSR row offsets
__device__ int   g_pos[MAX_N];        // scatter cursors
__device__ int   g_srcs[MAX_E];       // dst-sorted source ids
__device__ float g_dis[MAX_N];        // deg^-0.5
__device__ float g_h[(size_t)MAX_N * D];

// ---------------- histogram (= in-degree) ----------------

__global__ void k_zero(int n) {
    int i = blockIdx.x * blockDim.x + threadIdx.x;
    if (i < n) g_cnt[i] = 0;
}

__global__ void k_hist(const int* __restrict__ ei, int e) {
    int i = blockIdx.x * blockDim.x + threadIdx.x;
    if (i < e) {
        int s = ei[i];
        int d = ei[e + i];
        if (s != d) atomicAdd(&g_cnt[d], 1);
    }
}

// ---------------- 3-phase exclusive scan over g_cnt ----------------

__global__ __launch_bounds__(SCAN_BS) void k_scan1(int n) {
    __shared__ int sh[SCAN_BS];
    int t = threadIdx.x;
    int i = blockIdx.x * SCAN_BS + t;
    int v = (i < n) ? g_cnt[i] : 0;
    sh[t] = v;
    __syncthreads();
    #pragma unroll
    for (int off = 1; off < SCAN_BS; off <<= 1) {
        int x = (t >= off) ? sh[t - off] : 0;
        __syncthreads();
        if (t >= off) sh[t] += x;
        __syncthreads();
    }
    if (i < n) g_loc[i] = sh[t] - v;               // exclusive
    if (t == SCAN_BS - 1) g_bsum[blockIdx.x] = sh[t];
}

__global__ __launch_bounds__(MAX_NB) void k_scan2(int nb) {
    __shared__ int sh[MAX_NB];
    int t = threadIdx.x;
    int v = (t < nb) ? g_bsum[t] : 0;
    sh[t] = v;
    __syncthreads();
    #pragma unroll
    for (int off = 1; off < MAX_NB; off <<= 1) {
        int x = (t >= off) ? sh[t - off] : 0;
        __syncthreads();
        if (t >= off) sh[t] += x;
        __syncthreads();
    }
    if (t < nb) g_boff[t] = sh[t] - v;             // exclusive
}

__global__ void k_scan3(int n) {
    int i = blockIdx.x * blockDim.x + threadIdx.x;
    if (i < n) {
        int c = g_cnt[i];
        int off = g_loc[i] + g_boff[i / SCAN_BS];
        g_off[i] = off;
        g_pos[i] = off;
        g_dis[i] = rsqrtf(1.0f + (float)c);        // deg = 1 + cnt, always > 0
        if (i == n - 1) g_off[n] = off + c;
    }
}

// ---------------- sort edges by destination ----------------

__global__ void k_sortedges(const int* __restrict__ ei, int e) {
    int i = blockIdx.x * blockDim.x + threadIdx.x;
    if (i < e) {
        int s = ei[i];
        int d = ei[e + i];
        if (s != d) {
            int p = atomicAdd(&g_pos[d], 1);
            g_srcs[p] = s;
        }
    }
}

// ---------------- GEMM h = x @ W^T (writes g_h only) ----------------

__global__ __launch_bounds__(256) void k_gemm(
    const float* __restrict__ x, const float* __restrict__ w, int n)
{
    __shared__ float xs[64][65];   // xs[r][k]
    __shared__ float ws[64][65];   // ws[c][k]

    int tid = threadIdx.x;
    int tx = tid & 15;
    int ty = tid >> 4;
    int rbase = blockIdx.x * 64;

    #pragma unroll
    for (int l = tid; l < 4096; l += 256)
        ws[l >> 6][l & 63] = w[l];

    #pragma unroll
    for (int l = tid; l < 4096; l += 256) {
        int r = l >> 6, k = l & 63;
        int gr = rbase + r;
        xs[r][k] = (gr < n) ? x[(size_t)gr * D + k] : 0.0f;
    }
    __syncthreads();

    float acc[4][4] = {};
    int r0 = ty * 4, c0 = tx * 4;

    #pragma unroll 16
    for (int k = 0; k < 64; k++) {
        float xv[4], wv[4];
        #pragma unroll
        for (int i = 0; i < 4; i++) xv[i] = xs[r0 + i][k];
        #pragma unroll
        for (int j = 0; j < 4; j++) wv[j] = ws[c0 + j][k];
        #pragma unroll
        for (int i = 0; i < 4; i++)
            #pragma unroll
            for (int j = 0; j < 4; j++)
                acc[i][j] += xv[i] * wv[j];
    }

    #pragma unroll
    for (int i = 0; i < 4; i++) {
        int gr = rbase + r0 + i;
        if (gr < n) {
            #pragma unroll
            for (int j = 0; j < 4; j++)
                g_h[(size_t)gr * D + c0 + j] = acc[i][j];
        }
    }
}

// ---------------- aggregate: one warp per node, no atomics ----------------
// out[v] = bias + dis_v * ( dis_v * h[v] + sum_{s in nbrs(v)} dis_s * h[s] )

__global__ __launch_bounds__(256) void k_aggregate(
    const float* __restrict__ bias, float* __restrict__ out, int n)
{
    int wid  = (blockIdx.x * blockDim.x + threadIdx.x) >> 5;
    int lane = threadIdx.x & 31;
    if (wid >= n) return;

    float dv = g_dis[wid];
    const float2* hself = reinterpret_cast<const float2*>(g_h + (size_t)wid * D) + lane;
    float2 hv = *hself;
    float ax = dv * hv.x;
    float ay = dv * hv.y;

    int e   = g_off[wid];
    int end = g_off[wid + 1];

    for (; e + 2 <= end; e += 2) {
        int s0 = g_srcs[e];
        int s1 = g_srcs[e + 1];
        float d0 = g_dis[s0];
        float d1 = g_dis[s1];
        float2 a = *(reinterpret_cast<const float2*>(g_h + (size_t)s0 * D) + lane);
        float2 b = *(reinterpret_cast<const float2*>(g_h + (size_t)s1 * D) + lane);
        ax += d0 * a.x + d1 * b.x;
        ay += d0 * a.y + d1 * b.y;
    }
    if (e < end) {
        int s0 = g_srcs[e];
        float d0 = g_dis[s0];
        float2 a = *(reinterpret_cast<const float2*>(g_h + (size_t)s0 * D) + lane);
        ax += d0 * a.x;
        ay += d0 * a.y;
    }

    float2 bv = *(reinterpret_cast<const float2*>(bias) + lane);
    float2 res;
    res.x = bv.x + dv * ax;
    res.y = bv.y + dv * ay;
    *(reinterpret_cast<float2*>(out + (size_t)wid * D) + lane) = res;
}

// ---------------- launch ----------------

extern "C" void kernel_launch(void* const* d_in, const int* in_sizes, int n_in,
                              void* d_out, int out_size) {
    const float* x    = (const float*)d_in[0];
    const int*   ei   = (const int*)d_in[1];
    const float* w    = (const float*)d_in[2];
    const float* bias = (const float*)d_in[3];
    float* out = (float*)d_out;

    int n = in_sizes[0] / D;    // 100000
    int e = in_sizes[1] / 2;    // 1000000
    int nb = (n + SCAN_BS - 1) / SCAN_BS;

    // GEMM is independent of the degree/sort chain — front-load it.
    k_gemm<<<(n + 63) / 64, 256>>>(x, w, n);

    k_zero<<<(n + 255) / 256, 256>>>(n);
    k_hist<<<(e + 255) / 256, 256>>>(ei, e);
    k_scan1<<<nb, SCAN_BS>>>(n);
    k_scan2<<<1, MAX_NB>>>(nb);
    k_scan3<<<(n + 255) / 256, 256>>>(n);
    k_sortedges<<<(e + 255) / 256, 256>>>(ei, e);

    k_aggregate<<<((n * 32) + 255) / 256, 256>>>(bias, out, n);
}

// round 4
// speedup vs baseline: 1.4326x; 1.0385x over previous
#include <cuda_runtime.h>
#include <cstdint>

#define MAX_N 100000
#define MAX_E 1000000
#define D 64
#define PADX 76           // row pitch (words) for smem tiles: 16B-aligned, conflict-free
#define SCAN_CHUNK 2048
#define SCAN_BS 512

// Scratch (__device__ globals: allocation-free rule).
// Invariant: g_cnt is all-zero at entry to kernel_launch (zero-initialized at
// module load; k_scan3 re-zeros it after reading, every invocation).
__device__ int    g_cnt[MAX_N];
__device__ int    g_loc[MAX_N];
__device__ int    g_bsum[64];
__device__ int    g_boff[64];
__device__ int    g_off[MAX_N + 1];
__device__ int    g_pos[MAX_N];
__device__ float2 g_edata[MAX_E];     // (bitcast src id, dis[src])
__device__ float  g_dis[MAX_N];
__device__ float  g_h[(size_t)MAX_N * D];

// packed fp32x2 FMA: d.lo += a.lo*b.lo ; d.hi += a.hi*b.hi
__device__ __forceinline__ void ffma2(unsigned long long& d,
                                      unsigned long long a,
                                      unsigned long long b) {
    asm("fma.rn.f32x2 %0, %1, %2, %0;" : "+l"(d) : "l"(a), "l"(b));
}
__device__ __forceinline__ float unpack_sum(unsigned long long v) {
    float lo, hi;
    asm("mov.b64 {%0, %1}, %2;" : "=f"(lo), "=f"(hi) : "l"(v));
    return lo + hi;
}

// ---------------- fused GEMM (h = x @ W^T) + degree histogram ----------------
// Blocks [0, gemm_blocks): 64x64 output tile, 256 threads, f32x2 FMAs.
// Blocks [gemm_blocks, ...): grid-stride histogram over edges.

__global__ __launch_bounds__(256, 2) void k_gemm_hist(
    const float* __restrict__ x, const float* __restrict__ w,
    const int* __restrict__ ei, int n, int e, int gemm_blocks, int hist_blocks)
{
    __shared__ __align__(16) float xs[64 * PADX];
    __shared__ __align__(16) float ws[64 * PADX];

    int tid = threadIdx.x;

    if ((int)blockIdx.x >= gemm_blocks) {
        // ---- histogram branch ----
        int stride = hist_blocks * 256;
        for (int i = ((int)blockIdx.x - gemm_blocks) * 256 + tid; i < e; i += stride) {
            int s = ei[i];
            int d = ei[e + i];
            if (s != d) atomicAdd(&g_cnt[d], 1);
        }
        return;
    }

    // ---- GEMM branch ----
    int rbase = blockIdx.x * 64;
    int tx = tid & 7;        // col group: cols tx, tx+8, ..., tx+56
    int ty = tid >> 3;       // row group: rows ty*2, ty*2+1

    #pragma unroll
    for (int l = tid; l < 4096; l += 256)
        ws[(l >> 6) * PADX + (l & 63)] = w[l];

    #pragma unroll
    for (int l = tid; l < 4096; l += 256) {
        int r = l >> 6, k = l & 63;
        int gr = rbase + r;
        xs[r * PADX + k] = (gr < n) ? x[(size_t)gr * D + k] : 0.0f;
    }
    __syncthreads();

    unsigned long long acc[2][8];
    #pragma unroll
    for (int i = 0; i < 2; i++)
        #pragma unroll
        for (int j = 0; j < 8; j++) acc[i][j] = 0ULL;

    int r0 = ty * 2;

    #pragma unroll
    for (int k = 0; k < 64; k += 4) {
        ulonglong2 xv[2], wv[8];
        #pragma unroll
        for (int i = 0; i < 2; i++)
            xv[i] = *reinterpret_cast<const ulonglong2*>(&xs[(r0 + i) * PADX + k]);
        #pragma unroll
        for (int j = 0; j < 8; j++)
            wv[j] = *reinterpret_cast<const ulonglong2*>(&ws[(tx + j * 8) * PADX + k]);
        #pragma unroll
        for (int i = 0; i < 2; i++)
            #pragma unroll
            for (int j = 0; j < 8; j++) {
                ffma2(acc[i][j], xv[i].x, wv[j].x);
                ffma2(acc[i][j], xv[i].y, wv[j].y);
            }
    }

    #pragma unroll
    for (int i = 0; i < 2; i++) {
        int gr = rbase + r0 + i;
        if (gr < n) {
            #pragma unroll
            for (int j = 0; j < 8; j++)
                g_h[(size_t)gr * D + tx + j * 8] = unpack_sum(acc[i][j]);
        }
    }
}

// ---------------- scan phase 1: shfl-based, 2048 elems/block ----------------

__global__ __launch_bounds__(SCAN_BS) void k_scan1(int n) {
    __shared__ int wsum[16];
    int t = threadIdx.x;
    int base = blockIdx.x * SCAN_CHUNK + t * 4;

    int4 v = make_int4(0, 0, 0, 0);
    if (base + 3 < n) {
        v = *reinterpret_cast<const int4*>(&g_cnt[base]);
    } else {
        if (base     < n) v.x = g_cnt[base];
        if (base + 1 < n) v.y = g_cnt[base + 1];
        if (base + 2 < n) v.z = g_cnt[base + 2];
    }
    int s0 = v.x, s1 = s0 + v.y, s2 = s1 + v.z, s3 = s2 + v.w;

    int lane = t & 31, warp = t >> 5;
    int incl = s3;
    #pragma unroll
    for (int off = 1; off < 32; off <<= 1) {
        int u = __shfl_up_sync(0xffffffff, incl, off);
        if (lane >= off) incl += u;
    }
    if (lane == 31) wsum[warp] = incl;
    __syncthreads();
    if (warp == 0) {
        int wv = (lane < 16) ? wsum[lane] : 0;
        #pragma unroll
        for (int off = 1; off < 16; off <<= 1) {
            int u = __shfl_up_sync(0xffffffff, wv, off);
            if (lane >= off) wv += u;
        }
        if (lane < 16) wsum[lane] = wv;    // inclusive warp-sums scan
    }
    __syncthreads();

    int wexcl = warp ? wsum[warp - 1] : 0;
    int texcl = wexcl + incl - s3;          // exclusive prefix for this quad

    int4 o = make_int4(texcl, texcl + s0, texcl + s1, texcl + s2);
    if (base + 3 < n) {
        *reinterpret_cast<int4*>(&g_loc[base]) = o;
    } else {
        if (base     < n) g_loc[base]     = o.x;
        if (base + 1 < n) g_loc[base + 1] = o.y;
        if (base + 2 < n) g_loc[base + 2] = o.z;
    }
    if (t == SCAN_BS - 1) g_bsum[blockIdx.x] = wsum[15];   // single writer
}

// ---------------- scan phase 2: single block over <=64 block sums ----------------

__global__ __launch_bounds__(64) void k_scan2(int nb) {
    __shared__ int sh[64];
    int t = threadIdx.x;
    int v = (t < nb) ? g_bsum[t] : 0;
    sh[t] = v;
    __syncthreads();
    #pragma unroll
    for (int off = 1; off < 64; off <<= 1) {
        int u = (t >= off) ? sh[t - off] : 0;
        __syncthreads();
        if (t >= off) sh[t] += u;
        __syncthreads();
    }
    if (t < nb) g_boff[t] = sh[t] - v;
}

// ---------------- scan phase 3: offsets, cursors, dis; restore g_cnt=0 ----------------

__global__ void k_scan3(int n) {
    int i = blockIdx.x * blockDim.x + threadIdx.x;
    if (i < n) {
        int c = g_cnt[i];
        int off = g_loc[i] + g_boff[i / SCAN_CHUNK];
        g_off[i] = off;
        g_pos[i] = off;
        g_dis[i] = rsqrtf(1.0f + (float)c);   // deg = 1 + cnt > 0 always
        g_cnt[i] = 0;                          // restore invariant for next invocation
        if (i == n - 1) g_off[n] = off + c;
    }
}

// ---------------- sort edges by destination, pack (src, dis_src) ----------------

__global__ void k_sortedges(const int* __restrict__ ei, int e) {
    int i = blockIdx.x * blockDim.x + threadIdx.x;
    if (i < e) {
        int s = ei[i];
        int d = ei[e + i];
        if (s != d) {
            int p = atomicAdd(&g_pos[d], 1);
            g_edata[p] = make_float2(__int_as_float(s), g_dis[s]);
        }
    }
}

// ---------------- aggregate: one warp per node, atomic-free ----------------
// out[v] = bias + dis_v * ( dis_v * h[v] + sum_s dis_s * h[s] )

__global__ __launch_bounds__(256) void k_aggregate(
    const float* __restrict__ bias, float* __restrict__ out, int n)
{
    int wid  = (blockIdx.x * blockDim.x + threadIdx.x) >> 5;
    int lane = threadIdx.x & 31;
    if (wid >= n) return;

    float dv = g_dis[wid];
    float2 hv = *(reinterpret_cast<const float2*>(g_h + (size_t)wid * D) + lane);
    float ax = dv * hv.x;
    float ay = dv * hv.y;

    int ep  = g_off[wid];
    int end = g_off[wid + 1];

    for (; ep + 4 <= end; ep += 4) {
        float2 e0 = g_edata[ep];
        float2 e1 = g_edata[ep + 1];
        float2 e2 = g_edata[ep + 2];
        float2 e3 = g_edata[ep + 3];
        const float2* p0 = reinterpret_cast<const float2*>(g_h + (size_t)__float_as_int(e0.x) * D) + lane;
        const float2* p1 = reinterpret_cast<const float2*>(g_h + (size_t)__float_as_int(e1.x) * D) + lane;
        const float2* p2 = reinterpret_cast<const float2*>(g_h + (size_t)__float_as_int(e2.x) * D) + lane;
        const float2* p3 = reinterpret_cast<const float2*>(g_h + (size_t)__float_as_int(e3.x) * D) + lane;
        float2 a = __ldg(p0);
        float2 b = __ldg(p1);
        float2 c = __ldg(p2);
        float2 d = __ldg(p3);
        ax += e0.y * a.x + e1.y * b.x + e2.y * c.x + e3.y * d.x;
        ay += e0.y * a.y + e1.y * b.y + e2.y * c.y + e3.y * d.y;
    }
    for (; ep < end; ep++) {
        float2 e0 = g_edata[ep];
        float2 a = __ldg(reinterpret_cast<const float2*>(g_h + (size_t)__float_as_int(e0.x) * D) + lane);
        ax += e0.y * a.x;
        ay += e0.y * a.y;
    }

    float2 bv = *(reinterpret_cast<const float2*>(bias) + lane);
    float2 res;
    res.x = bv.x + dv * ax;
    res.y = bv.y + dv * ay;
    *(reinterpret_cast<float2*>(out + (size_t)wid * D) + lane) = res;
}

// ---------------- launch ----------------

extern "C" void kernel_launch(void* const* d_in, const int* in_sizes, int n_in,
                              void* d_out, int out_size) {
    const float* x    = (const float*)d_in[0];
    const int*   ei   = (const int*)d_in[1];
    const float* w    = (const float*)d_in[2];
    const float* bias = (const float*)d_in[3];
    float* out = (float*)d_out;

    int n = in_sizes[0] / D;    // 100000
    int e = in_sizes[1] / 2;    // 1000000

    int gemm_blocks = (n + 63) / 64;
    int hist_blocks = 1184;     // 8 * 148, grid-stride
    int nb = (n + SCAN_CHUNK - 1) / SCAN_CHUNK;

    k_gemm_hist<<<gemm_blocks + hist_blocks, 256>>>(x, w, ei, n, e, gemm_blocks, hist_blocks);
    k_scan1<<<nb, SCAN_BS>>>(n);
    k_scan2<<<1, 64>>>(nb);
    k_scan3<<<(n + 255) / 256, 256>>>(n);
    k_sortedges<<<(e + 255) / 256, 256>>>(ei, e);
    k_aggregate<<<((n * 32) + 255) / 256, 256>>>(bias, out, n);
}

// round 5
// speedup vs baseline: 1.4597x; 1.0189x over previous
#include <cuda_runtime.h>
#include <cstdint>

#define MAX_N 100000
#define MAX_E 1000000
#define D 64
#define PADX 76           // smem row pitch (words): 16B-aligned, conflict-free
#define NBUILD 148        // one build block per SM (bids 0..147 -> wave-1 resident)
#define BT 256

// Scratch (__device__ globals; allocation-free rule).
// Invariants maintained across invocations: g_cnt all-zero (re-zeroed in phase C),
// g_bar all-zero (reset by last block each run).
__device__ int    g_cnt[MAX_N];
__device__ int    g_loc[MAX_N];
__device__ int    g_bsum[NBUILD];
__device__ int    g_boff[NBUILD];
__device__ int    g_off[MAX_N + 1];
__device__ int    g_pos[MAX_N];
__device__ float2 g_edata[MAX_E];     // (bitcast src id, dis[src])
__device__ float  g_dis[MAX_N];
__device__ float  g_h[(size_t)MAX_N * D];
__device__ int    g_bar[8];

// packed fp32x2 FMA helpers
__device__ __forceinline__ void ffma2(unsigned long long& d,
                                      unsigned long long a,
                                      unsigned long long b) {
    asm("fma.rn.f32x2 %0, %1, %2, %0;" : "+l"(d) : "l"(a), "l"(b));
}
__device__ __forceinline__ float unpack_sum(unsigned long long v) {
    float lo, hi;
    asm("mov.b64 {%0, %1}, %2;" : "=f"(lo), "=f"(hi) : "l"(v));
    return lo + hi;
}

// Grid barrier among the NBUILD build blocks only (all co-resident: bids 0..147
// land on 148 distinct SMs in wave 1, so spinning cannot deadlock).
__device__ __forceinline__ void build_bar(int idx) {
    __syncthreads();
    if (threadIdx.x == 0) {
        __threadfence();
        atomicAdd(&g_bar[idx], 1);
        while (*((volatile int*)&g_bar[idx]) < NBUILD) __nanosleep(32);
    }
    __syncthreads();
}

// Block-wide exclusive scan (256 threads), returns exclusive prefix; total via ref.
__device__ __forceinline__ int block_scan(int v, int* sh8, int& total) {
    int lane = threadIdx.x & 31, warp = threadIdx.x >> 5;
    int incl = v;
    #pragma unroll
    for (int o = 1; o < 32; o <<= 1) {
        int u = __shfl_up_sync(0xffffffff, incl, o);
        if (lane >= o) incl += u;
    }
    if (lane == 31) sh8[warp] = incl;
    __syncthreads();
    if (warp == 0) {
        int wv = (lane < 8) ? sh8[lane] : 0;
        #pragma unroll
        for (int o = 1; o < 8; o <<= 1) {
            int u = __shfl_up_sync(0xffffffff, wv, o);
            if (lane >= o) wv += u;
        }
        if (lane < 8) sh8[lane] = wv;   // inclusive scan of warp sums
    }
    __syncthreads();
    int wexcl = warp ? sh8[warp - 1] : 0;
    total = sh8[7];
    __syncthreads();                     // sh8 reusable after return
    return wexcl + incl - v;
}

// ---------------- fused kernel ----------------
// bids [0, NBUILD): persistent build blocks: hist -> bar -> local scan -> bar ->
//                   block0 scans block sums -> bar -> write-out -> bar -> sort -> reset.
// bids [NBUILD, ...): one 64x64 GEMM tile each (h = x @ W^T, f32x2 FMAs).

__global__ __launch_bounds__(BT) void k_fused(
    const float* __restrict__ x, const float* __restrict__ w,
    const int* __restrict__ ei, int n, int e)
{
    __shared__ __align__(16) float xs[64 * PADX];
    __shared__ __align__(16) float ws[64 * PADX];
    __shared__ int sh8[8];

    int tid = threadIdx.x;
    int bid = blockIdx.x;

    if (bid >= NBUILD) {
        // ================= GEMM tile =================
        int rbase = (bid - NBUILD) * 64;
        int tx = tid & 7;        // col group: cols tx, tx+8, ..., tx+56
        int ty = tid >> 3;       // row group: rows ty*2, ty*2+1

        #pragma unroll
        for (int l = tid; l < 4096; l += BT)
            ws[(l >> 6) * PADX + (l & 63)] = w[l];

        #pragma unroll
        for (int l = tid; l < 4096; l += BT) {
            int r = l >> 6, k = l & 63;
            int gr = rbase + r;
            xs[r * PADX + k] = (gr < n) ? x[(size_t)gr * D + k] : 0.0f;
        }
        __syncthreads();

        unsigned long long acc[2][8];
        #pragma unroll
        for (int i = 0; i < 2; i++)
            #pragma unroll
            for (int j = 0; j < 8; j++) acc[i][j] = 0ULL;

        int r0 = ty * 2;

        #pragma unroll
        for (int k = 0; k < 64; k += 4) {
            ulonglong2 xv[2], wv[8];
            #pragma unroll
            for (int i = 0; i < 2; i++)
                xv[i] = *reinterpret_cast<const ulonglong2*>(&xs[(r0 + i) * PADX + k]);
            #pragma unroll
            for (int j = 0; j < 8; j++)
                wv[j] = *reinterpret_cast<const ulonglong2*>(&ws[(tx + j * 8) * PADX + k]);
            #pragma unroll
            for (int i = 0; i < 2; i++)
                #pragma unroll
                for (int j = 0; j < 8; j++) {
                    ffma2(acc[i][j], xv[i].x, wv[j].x);
                    ffma2(acc[i][j], xv[i].y, wv[j].y);
                }
        }

        #pragma unroll
        for (int i = 0; i < 2; i++) {
            int gr = rbase + r0 + i;
            if (gr < n) {
                #pragma unroll
                for (int j = 0; j < 8; j++)
                    g_h[(size_t)gr * D + tx + j * 8] = unpack_sum(acc[i][j]);
            }
        }
        return;
    }

    // ================= build block =================
    // Phase 0: degree histogram (grid-stride over edges, NBUILD*BT threads)
    {
        int stride = NBUILD * BT;
        for (int i = bid * BT + tid; i < e; i += stride) {
            int s = ei[i];
            int d = ei[e + i];
            if (s != d) atomicAdd(&g_cnt[d], 1);
        }
    }
    build_bar(0);

    // Phase A: local exclusive scan of this block's node chunk
    int chunk = (n + NBUILD - 1) / NBUILD;
    int start = bid * chunk;
    int stop  = min(start + chunk, n);
    int carry = 0;
    for (int base = start; base < stop; base += BT) {
        int i = base + tid;
        int v = (i < stop) ? g_cnt[i] : 0;
        int total;
        int excl = block_scan(v, sh8, total);
        if (i < stop) g_loc[i] = carry + excl;
        carry += total;
    }
    if (tid == 0) g_bsum[bid] = carry;
    build_bar(1);

    // Phase B: block 0 exclusive-scans the NBUILD block sums
    if (bid == 0) {
        int v = (tid < NBUILD) ? g_bsum[tid] : 0;
        int total;
        int excl = block_scan(v, sh8, total);
        if (tid < NBUILD) g_boff[tid] = excl;
    }
    build_bar(2);

    // Phase C: write offsets/cursors/dis, restore g_cnt = 0
    {
        int boff = g_boff[bid];
        for (int base = start; base < stop; base += BT) {
            int i = base + tid;
            if (i < stop) {
                int c = g_cnt[i];
                int off = g_loc[i] + boff;
                g_off[i] = off;
                g_pos[i] = off;
                g_dis[i] = rsqrtf(1.0f + (float)c);   // deg = 1 + cnt > 0
                g_cnt[i] = 0;
                if (i == n - 1) g_off[n] = off + c;
            }
        }
    }
    build_bar(3);

    // Phase D: dst-sort edges, packing (src, dis[src])
    {
        int stride = NBUILD * BT;
        for (int i = bid * BT + tid; i < e; i += stride) {
            int s = ei[i];
            int d = ei[e + i];
            if (s != d) {
                int p = atomicAdd(&g_pos[d], 1);
                g_edata[p] = make_float2(__int_as_float(s), g_dis[s]);
            }
        }
    }

    // Reset barrier counters for the next (graph-replayed) invocation.
    __syncthreads();
    if (tid == 0) {
        __threadfence();
        int old = atomicAdd(&g_bar[4], 1);
        if (old == NBUILD - 1) {
            g_bar[0] = 0; g_bar[1] = 0; g_bar[2] = 0;
            g_bar[3] = 0; g_bar[4] = 0;
            __threadfence();
        }
    }
}

// ---------------- aggregate: one warp per node, atomic-free ----------------
// out[v] = bias + dis_v * ( dis_v * h[v] + sum_s dis_s * h[s] )

__global__ __launch_bounds__(256) void k_aggregate(
    const float* __restrict__ bias, float* __restrict__ out, int n)
{
    int wid  = (blockIdx.x * blockDim.x + threadIdx.x) >> 5;
    int lane = threadIdx.x & 31;
    if (wid >= n) return;

    float dv = g_dis[wid];
    float2 hv = *(reinterpret_cast<const float2*>(g_h + (size_t)wid * D) + lane);
    float ax = dv * hv.x;
    float ay = dv * hv.y;

    int ep  = g_off[wid];
    int end = g_off[wid + 1];

    for (; ep + 4 <= end; ep += 4) {
        float2 e0 = g_edata[ep];
        float2 e1 = g_edata[ep + 1];
        float2 e2 = g_edata[ep + 2];
        float2 e3 = g_edata[ep + 3];
        const float2* p0 = reinterpret_cast<const float2*>(g_h + (size_t)__float_as_int(e0.x) * D) + lane;
        const float2* p1 = reinterpret_cast<const float2*>(g_h + (size_t)__float_as_int(e1.x) * D) + lane;
        const float2* p2 = reinterpret_cast<const float2*>(g_h + (size_t)__float_as_int(e2.x) * D) + lane;
        const float2* p3 = reinterpret_cast<const float2*>(g_h + (size_t)__float_as_int(e3.x) * D) + lane;
        float2 a = __ldg(p0);
        float2 b = __ldg(p1);
        float2 c = __ldg(p2);
        float2 d = __ldg(p3);
        ax += e0.y * a.x + e1.y * b.x + e2.y * c.x + e3.y * d.x;
        ay += e0.y * a.y + e1.y * b.y + e2.y * c.y + e3.y * d.y;
    }
    for (; ep < end; ep++) {
        float2 e0 = g_edata[ep];
        float2 a = __ldg(reinterpret_cast<const float2*>(g_h + (size_t)__float_as_int(e0.x) * D) + lane);
        ax += e0.y * a.x;
        ay += e0.y * a.y;
    }

    float2 bv = *(reinterpret_cast<const float2*>(bias) + lane);
    float2 res;
    res.x = bv.x + dv * ax;
    res.y = bv.y + dv * ay;
    *(reinterpret_cast<float2*>(out + (size_t)wid * D) + lane) = res;
}

// ---------------- launch ----------------

extern "C" void kernel_launch(void* const* d_in, const int* in_sizes, int n_in,
                              void* d_out, int out_size) {
    const float* x    = (const float*)d_in[0];
    const int*   ei   = (const int*)d_in[1];
    const float* w    = (const float*)d_in[2];
    const float* bias = (const float*)d_in[3];
    float* out = (float*)d_out;

    int n = in_sizes[0] / D;    // 100000
    int e = in_sizes[1] / 2;    // 1000000

    int gemm_blocks = (n + 63) / 64;   // 1563

    k_fused<<<NBUILD + gemm_blocks, BT>>>(x, w, ei, n, e);
    k_aggregate<<<((n * 32) + 255) / 256, 256>>>(bias, out, n);
}

// round 7
// speedup vs baseline: 1.5016x; 1.0287x over previous
#include <cuda_runtime.h>
#include <cstdint>

#define MAX_N 100000
#define MAX_E 1000000
#define D 64
#define PADX 76           // smem row pitch (words): 16B-aligned, conflict-free
#define NBUILD 148        // one build block per SM (bids 0..147 -> wave-1 resident)
#define BT 256

// Scratch (__device__ globals; allocation-free rule).
// Invariants across invocations: g_cnt all-zero (re-zeroed in phase C),
// g_bar all-zero (reset by last block each run).
__device__ int    g_cnt[MAX_N];
__device__ int    g_loc[MAX_N];
__device__ int    g_bsum[NBUILD];
__device__ int    g_boff[NBUILD];
__device__ int    g_off[MAX_N + 1];
__device__ int    g_pos[MAX_N];
__device__ float2 g_edata[MAX_E];     // (bitcast src id, dis[src])
__device__ float  g_dis[MAX_N];
__device__ float  g_h[(size_t)MAX_N * D];
__device__ int    g_bar[8];

// packed fp32x2 FMA helpers
__device__ __forceinline__ void ffma2(unsigned long long& d,
                                      unsigned long long a,
                                      unsigned long long b) {
    asm("fma.rn.f32x2 %0, %1, %2, %0;" : "+l"(d) : "l"(a), "l"(b));
}
__device__ __forceinline__ float unpack_sum(unsigned long long v) {
    float lo, hi;
    asm("mov.b64 {%0, %1}, %2;" : "=f"(lo), "=f"(hi) : "l"(v));
    return lo + hi;
}

// Grid barrier among the NBUILD build blocks only (co-resident: one per SM in
// wave 1; smem/reg budget guarantees >=2 CTAs/SM so bids 0..147 are resident).
__device__ __forceinline__ void build_bar(int idx) {
    __syncthreads();
    if (threadIdx.x == 0) {
        __threadfence();                       // release
        atomicAdd(&g_bar[idx], 1);
        while (*((volatile int*)&g_bar[idx]) < NBUILD) __nanosleep(32);
        __threadfence();                       // acquire
    }
    __syncthreads();
}

// Block-wide exclusive scan (256 threads).
__device__ __forceinline__ int block_scan(int v, int* sh8, int& total) {
    int lane = threadIdx.x & 31, warp = threadIdx.x >> 5;
    int incl = v;
    #pragma unroll
    for (int o = 1; o < 32; o <<= 1) {
        int u = __shfl_up_sync(0xffffffff, incl, o);
        if (lane >= o) incl += u;
    }
    if (lane == 31) sh8[warp] = incl;
    __syncthreads();
    if (warp == 0) {
        int wv = (lane < 8) ? sh8[lane] : 0;
        #pragma unroll
        for (int o = 1; o < 8; o <<= 1) {
            int u = __shfl_up_sync(0xffffffff, wv, o);
            if (lane >= o) wv += u;
        }
        if (lane < 8) sh8[lane] = wv;
    }
    __syncthreads();
    int wexcl = warp ? sh8[warp - 1] : 0;
    total = sh8[7];
    __syncthreads();
    return wexcl + incl - v;
}

// ---------------- fused build + GEMM kernel ----------------
// bids [0, NBUILD): persistent build blocks: hist -> bar -> scan -> bar ->
//                   block0 scans sums -> bar -> write-out -> bar -> sort -> reset.
// bids [NBUILD, ...): one 64x64 GEMM tile each (h = x @ W^T, f32x2 FMAs),
//                     running concurrently with the build chain.

__global__ __launch_bounds__(BT) void k_fused(
    const float* __restrict__ x, const float* __restrict__ w,
    const int* __restrict__ ei, int n, int e)
{
    __shared__ __align__(16) float xs[64 * PADX];
    __shared__ __align__(16) float ws[64 * PADX];
    __shared__ int sh8[8];

    int tid = threadIdx.x;
    int bid = blockIdx.x;

    if (bid >= NBUILD) {
        // ================= GEMM tile: h = x @ W^T =================
        int rbase = (bid - NBUILD) * 64;
        int tx = tid & 7;
        int ty = tid >> 3;

        #pragma unroll
        for (int l = tid; l < 4096; l += BT)
            ws[(l >> 6) * PADX + (l & 63)] = w[l];

        #pragma unroll
        for (int l = tid; l < 4096; l += BT) {
            int r = l >> 6, k = l & 63;
            int gr = rbase + r;
            xs[r * PADX + k] = (gr < n) ? x[(size_t)gr * D + k] : 0.0f;
        }
        __syncthreads();

        unsigned long long acc[2][8];
        #pragma unroll
        for (int i = 0; i < 2; i++)
            #pragma unroll
            for (int j = 0; j < 8; j++) acc[i][j] = 0ULL;

        int r0 = ty * 2;

        #pragma unroll
        for (int k = 0; k < 64; k += 4) {
            ulonglong2 xv[2], wv[8];
            #pragma unroll
            for (int i = 0; i < 2; i++)
                xv[i] = *reinterpret_cast<const ulonglong2*>(&xs[(r0 + i) * PADX + k]);
            #pragma unroll
            for (int j = 0; j < 8; j++)
                wv[j] = *reinterpret_cast<const ulonglong2*>(&ws[(tx + j * 8) * PADX + k]);
            #pragma unroll
            for (int i = 0; i < 2; i++)
                #pragma unroll
                for (int j = 0; j < 8; j++) {
                    ffma2(acc[i][j], xv[i].x, wv[j].x);
                    ffma2(acc[i][j], xv[i].y, wv[j].y);
                }
        }

        #pragma unroll
        for (int i = 0; i < 2; i++) {
            int gr = rbase + r0 + i;
            if (gr < n) {
                #pragma unroll
                for (int j = 0; j < 8; j++)
                    g_h[(size_t)gr * D + tx + j * 8] = unpack_sum(acc[i][j]);
            }
        }
        return;
    }

    // ================= build block =================
    // Phase 0: degree histogram
    {
        int stride = NBUILD * BT;
        #pragma unroll 4
        for (int i = bid * BT + tid; i < e; i += stride) {
            int s = __ldg(&ei[i]);
            int d = __ldg(&ei[e + i]);
            if (s != d) atomicAdd(&g_cnt[d], 1);
        }
    }
    build_bar(0);

    // Phase A: local exclusive scan of this block's node chunk
    int chunk = (n + NBUILD - 1) / NBUILD;
    int start = bid * chunk;
    int stop  = min(start + chunk, n);
    int carry = 0;
    for (int base = start; base < stop; base += BT) {
        int i = base + tid;
        int v = (i < stop) ? g_cnt[i] : 0;
        int total;
        int excl = block_scan(v, sh8, total);
        if (i < stop) g_loc[i] = carry + excl;
        carry += total;
    }
    if (tid == 0) g_bsum[bid] = carry;
    build_bar(1);

    // Phase B: block 0 scans the block sums
    if (bid == 0) {
        int v = (tid < NBUILD) ? g_bsum[tid] : 0;
        int total;
        int excl = block_scan(v, sh8, total);
        if (tid < NBUILD) g_boff[tid] = excl;
    }
    build_bar(2);

    // Phase C: offsets, cursors, dis; restore g_cnt = 0
    {
        int boff = g_boff[bid];
        for (int base = start; base < stop; base += BT) {
            int i = base + tid;
            if (i < stop) {
                int c = g_cnt[i];
                int off = g_loc[i] + boff;
                g_off[i] = off;
                g_pos[i] = off;
                g_dis[i] = rsqrtf(1.0f + (float)c);
                g_cnt[i] = 0;
                if (i == n - 1) g_off[n] = off + c;
            }
        }
    }
    build_bar(3);

    // Phase D: dst-sort edges, packing (src, dis[src])
    {
        int stride = NBUILD * BT;
        #pragma unroll 4
        for (int i = bid * BT + tid; i < e; i += stride) {
            int s = __ldg(&ei[i]);
            int d = __ldg(&ei[e + i]);
            if (s != d) {
                int p = atomicAdd(&g_pos[d], 1);
                g_edata[p] = make_float2(__int_as_float(s), g_dis[s]);
            }
        }
    }

    // Reset barrier counters for the next invocation.
    __syncthreads();
    if (tid == 0) {
        __threadfence();
        int old = atomicAdd(&g_bar[4], 1);
        if (old == NBUILD - 1) {
            g_bar[0] = 0; g_bar[1] = 0; g_bar[2] = 0;
            g_bar[3] = 0; g_bar[4] = 0;
            __threadfence();
        }
    }
}

// ---------------- aggregate: warp/node, half-warp/edge, float4 lanes ----------------
// out[v] = bias + dis_v * ( dis_v * h[v] + sum_s dis_s * h[s] )
// Lanes 0-15 = edge stream A, lanes 16-31 = edge stream B. Each lane loads a
// float4 (16 lanes x 16B = 256B per row). shfl_xor(16) folds the two streams.

__global__ __launch_bounds__(256) void k_aggregate(
    const float* __restrict__ bias, float* __restrict__ out, int n)
{
    int wid  = (blockIdx.x * blockDim.x + threadIdx.x) >> 5;
    int lane = threadIdx.x & 31;
    if (wid >= n) return;

    int half = lane >> 4;        // 0: stream A, 1: stream B
    int fl   = lane & 15;        // float4 slot: features [4*fl, 4*fl+4)

    float dv = g_dis[wid];
    float4 acc = make_float4(0.f, 0.f, 0.f, 0.f);

    // self term into stream A only
    if (half == 0) {
        float4 hv = __ldg(reinterpret_cast<const float4*>(g_h + (size_t)wid * D) + fl);
        acc.x = dv * hv.x; acc.y = dv * hv.y; acc.z = dv * hv.z; acc.w = dv * hv.w;
    }

    int ep  = g_off[wid];
    int end = g_off[wid + 1];

    // main: 8 edges per pass (4 steps x 2 streams), 4 LDG.128 in flight
    for (; ep + 8 <= end; ep += 8) {
        float2 pr[4];
        float4 v[4];
        #pragma unroll
        for (int u = 0; u < 4; u++) {
            pr[u] = __ldg(&g_edata[ep + u * 2 + half]);
            v[u] = __ldg(reinterpret_cast<const float4*>(
                       g_h + (size_t)__float_as_int(pr[u].x) * D) + fl);
        }
        #pragma unroll
        for (int u = 0; u < 4; u++) {
            acc.x += pr[u].y * v[u].x;
            acc.y += pr[u].y * v[u].y;
            acc.z += pr[u].y * v[u].z;
            acc.w += pr[u].y * v[u].w;
        }
    }
    // 2-edge steps
    for (; ep + 2 <= end; ep += 2) {
        float2 pr = __ldg(&g_edata[ep + half]);
        float4 v = __ldg(reinterpret_cast<const float4*>(
                       g_h + (size_t)__float_as_int(pr.x) * D) + fl);
        acc.x += pr.y * v.x;
        acc.y += pr.y * v.y;
        acc.z += pr.y * v.z;
        acc.w += pr.y * v.w;
    }
    // odd remainder: stream A only
    if (ep < end && half == 0) {
        float2 pr = __ldg(&g_edata[ep]);
        float4 v = __ldg(reinterpret_cast<const float4*>(
                       g_h + (size_t)__float_as_int(pr.x) * D) + fl);
        acc.x += pr.y * v.x;
        acc.y += pr.y * v.y;
        acc.z += pr.y * v.z;
        acc.w += pr.y * v.w;
    }

    // fold streams A+B
    acc.x += __shfl_xor_sync(0xffffffff, acc.x, 16);
    acc.y += __shfl_xor_sync(0xffffffff, acc.y, 16);
    acc.z += __shfl_xor_sync(0xffffffff, acc.z, 16);
    acc.w += __shfl_xor_sync(0xffffffff, acc.w, 16);

    if (half == 0) {
        float4 bv = __ldg(reinterpret_cast<const float4*>(bias) + fl);
        float4 res;
        res.x = bv.x + dv * acc.x;
        res.y = bv.y + dv * acc.y;
        res.z = bv.z + dv * acc.z;
        res.w = bv.w + dv * acc.w;
        *(reinterpret_cast<float4*>(out + (size_t)wid * D) + fl) = res;
    }
}

// ---------------- launch ----------------

extern "C" void kernel_launch(void* const* d_in, const int* in_sizes, int n_in,
                              void* d_out, int out_size) {
    const float* x    = (const float*)d_in[0];
    const int*   ei   = (const int*)d_in[1];
    const float* w    = (const float*)d_in[2];
    const float* bias = (const float*)d_in[3];
    float* out = (float*)d_out;

    int n = in_sizes[0] / D;    // 100000
    int e = in_sizes[1] / 2;    // 1000000

    int gemm_blocks = (n + 63) / 64;   // 1563

    k_fused<<<NBUILD + gemm_blocks, BT>>>(x, w, ei, n, e);
    k_aggregate<<<((n + 7) / 8), 256>>>(bias, out, n);
}